// round 7
// baseline (speedup 1.0000x reference)
#include <cuda_runtime.h>

// Chamfer distance, B=2, N=8192. Symmetric brute force: each pair computed ONCE,
// feeding BOTH row-min (per-gt) and col-min (per-pred).
// w_ij = c_i + c_j - q_i.p_j (c = 0.5||.||^2); dist^2 = max(2w, 0); sqrt after min.
// Inner: per 2 pairs = 1 FADD2 + 3 FFMA2 (fma pipe) + 4 FMNMX (alu pipe).
// ITILE=8 amortizes the lane-skewed shared traffic below the FFMA2 floor.

#define BATCH   2
#define NPTS    8192
#define THREADS 128
#define ITILE   8
#define IBLK    (THREADS * ITILE)   // 1024 gt rows per CTA
#define ITILES  (NPTS / IBLK)       // 8
#define JSPLITS 36                  // pred pair-range splits
#define TOTP    (NPTS / 2)          // 4096 pred pairs per batch
#define MAXP    120                 // >= ceil(4096/36)=114, padded
#define NCTA    (BATCH * ITILES * JSPLITS)   // 576 <= 592 resident @4/SM

__device__ float g_rowpart[BATCH * JSPLITS * NPTS];   // 2.36 MB
__device__ float g_colpart[BATCH * ITILES  * NPTS];   // 0.5 MB
__device__ float g_blocksum[128];

typedef unsigned long long u64;

__device__ __forceinline__ u64 pack2(float lo, float hi) {
    u64 d; asm("mov.b64 %0, {%1,%2};" : "=l"(d) : "f"(lo), "f"(hi)); return d;
}
__device__ __forceinline__ void unpack2(u64 d, float& lo, float& hi) {
    asm("mov.b64 {%0,%1}, %2;" : "=f"(lo), "=f"(hi) : "l"(d));
}
__device__ __forceinline__ u64 fma2(u64 a, u64 b, u64 c) {
    u64 d; asm("fma.rn.f32x2 %0, %1, %2, %3;" : "=l"(d) : "l"(a), "l"(b), "l"(c));
    return d;
}
__device__ __forceinline__ u64 add2(u64 a, u64 b) {
    u64 d; asm("add.rn.f32x2 %0, %1, %2;" : "=l"(d) : "l"(a), "l"(b));
    return d;
}

__global__ __launch_bounds__(THREADS, 4)
void chamfer_pass(const float* __restrict__ pred, const float* __restrict__ gt) {
    const int bid = blockIdx.x;
    const int b   = bid / (ITILES * JSPLITS);
    const int r   = bid - b * (ITILES * JSPLITS);
    const int it  = r / JSPLITS;
    const int js  = r - it * JSPLITS;
    const int ibase  = it * IBLK;
    const int pstart = (js * TOTP) / JSPLITS;
    const int pend   = ((js + 1) * TOTP) / JSPLITS;
    const int npairs = pend - pstart;           // 113 or 114 (> 32)
    const int tid = threadIdx.x;

    __shared__ float4 sxy[MAXP];
    __shared__ float4 szc[MAXP];
    __shared__ float2 scm[4][MAXP];   // per-warp col-min rows

    if (tid < npairs) {
        const float* p = pred + ((size_t)b * NPTS + 2 * (pstart + tid)) * 3;
        float x0 = p[0], y0 = p[1], z0 = p[2];
        float x1 = p[3], y1 = p[4], z1 = p[5];
        sxy[tid] = make_float4(x0, x1, y0, y1);
        szc[tid] = make_float4(z0, z1,
                               0.5f * (x0 * x0 + y0 * y0 + z0 * z0),
                               0.5f * (x1 * x1 + y1 * y1 + z1 * z1));
    }
    if (tid < MAXP) {
#pragma unroll
        for (int u = 0; u < 4; u++)
            scm[u][tid] = make_float2(3.4e38f, 3.4e38f);
    }

    // i-side (gt) in registers, negated + replicated for f32x2.
    u64 nix2[ITILE], niy2[ITILE], niz2[ITILE], ci2[ITILE];
    float rmA[ITILE], rmB[ITILE];
#pragma unroll
    for (int k = 0; k < ITILE; k++) {
        const float* g = gt + ((size_t)b * NPTS + ibase + tid + k * THREADS) * 3;
        float x = g[0], y = g[1], z = g[2];
        nix2[k] = pack2(-x, -x);
        niy2[k] = pack2(-y, -y);
        niz2[k] = pack2(-z, -z);
        float c = 0.5f * (x * x + y * y + z * z);
        ci2[k] = pack2(c, c);
        rmA[k] = 3.4e38f;
        rmB[k] = 3.4e38f;
    }
    __syncthreads();

    const int w    = tid >> 5;
    const int lane = tid & 31;
    const ulonglong2* __restrict__ pxy = reinterpret_cast<const ulonglong2*>(sxy);
    const ulonglong2* __restrict__ pzc = reinterpret_cast<const ulonglong2*>(szc);
    float2* __restrict__ cmrow = scm[w];

    // Lane-skewed jp walk: at each step all lanes hold distinct jp (npairs > 32)
    // -> race-free col RMW within the warp's private row.
    int jp = lane;
#pragma unroll 2
    for (int s = 0; s < npairs; s++) {
        ulonglong2 vxy = pxy[jp];       // {x0,x1},{y0,y1}
        ulonglong2 vzc = pzc[jp];       // {z0,z1},{c0,c1}
        float2 cm = cmrow[jp];
        float ca0 = cm.x, ca1 = cm.y;
#pragma unroll
        for (int k = 0; k < ITILE; k++) {
            u64 w2 = fma2(niz2[k], vzc.x, add2(ci2[k], vzc.y));
            w2 = fma2(niy2[k], vxy.y, w2);
            w2 = fma2(nix2[k], vxy.x, w2);
            float w0, w1; unpack2(w2, w0, w1);
            rmA[k] = fminf(rmA[k], w0);
            rmB[k] = fminf(rmB[k], w1);
            ca0 = fminf(ca0, w0);
            ca1 = fminf(ca1, w1);
        }
        cmrow[jp] = make_float2(ca0, ca1);
        jp++; if (jp == npairs) jp = 0;
    }
    __syncthreads();

    // Row-min partials (min over this CTA's j range), coalesced.
    float* rout = g_rowpart + ((size_t)(b * JSPLITS + js)) * NPTS + ibase;
#pragma unroll
    for (int k = 0; k < ITILE; k++)
        rout[tid + k * THREADS] = fminf(rmA[k], rmB[k]);

    // Col-min partials: combine 4 warp rows, write float2 per pair.
    if (tid < npairs) {
        float2 m = scm[0][tid];
#pragma unroll
        for (int u = 1; u < 4; u++) {
            float2 v = scm[u][tid];
            m.x = fminf(m.x, v.x);
            m.y = fminf(m.y, v.y);
        }
        float2* cout = reinterpret_cast<float2*>(
            g_colpart + ((size_t)(b * ITILES + it)) * NPTS + 2 * (pstart + tid));
        cout[0] = m;
    }
}

// Stage 1: 32768 tasks. First 16384 = row side (min over 36 splits),
// rest = col side (min over 8 itiles). All strided reads are warp-coalesced.
__global__ __launch_bounds__(256)
void chamfer_reduce_a() {
    __shared__ float ssum[256];
    const int qid = blockIdx.x * 256 + threadIdx.x;   // 0..32767
    float mv = 3.4e38f;
    if (qid < BATCH * NPTS) {
        const int b = qid >> 13, i = qid & (NPTS - 1);
        const float* p = g_rowpart + (size_t)b * JSPLITS * NPTS + i;
#pragma unroll 6
        for (int t = 0; t < JSPLITS; t++) mv = fminf(mv, p[(size_t)t * NPTS]);
    } else {
        const int q = qid - BATCH * NPTS;
        const int b = q >> 13, j = q & (NPTS - 1);
        const float* p = g_colpart + (size_t)b * ITILES * NPTS + j;
#pragma unroll
        for (int t = 0; t < ITILES; t++) mv = fminf(mv, p[(size_t)t * NPTS]);
    }
    ssum[threadIdx.x] = sqrtf(fmaxf(2.0f * mv, 0.0f));
    __syncthreads();
    for (int s = 128; s > 0; s >>= 1) {
        if (threadIdx.x < s) ssum[threadIdx.x] += ssum[threadIdx.x + s];
        __syncthreads();
    }
    if (threadIdx.x == 0) g_blocksum[blockIdx.x] = ssum[0];
}

__global__ void chamfer_reduce_b(float* __restrict__ out) {
    __shared__ float s[128];
    s[threadIdx.x] = g_blocksum[threadIdx.x];
    __syncthreads();
    for (int st = 64; st > 0; st >>= 1) {
        if (threadIdx.x < st) s[threadIdx.x] += s[threadIdx.x + st];
        __syncthreads();
    }
    if (threadIdx.x == 0) out[0] = s[0] / (float)(BATCH * NPTS);
}

extern "C" void kernel_launch(void* const* d_in, const int* in_sizes, int n_in,
                              void* d_out, int out_size) {
    const float* pred = (const float*)d_in[0];
    const float* gt   = (const float*)d_in[1];
    float* out        = (float*)d_out;

    chamfer_pass<<<NCTA, THREADS>>>(pred, gt);
    chamfer_reduce_a<<<128, 256>>>();
    chamfer_reduce_b<<<1, 128>>>(out);
}